// round 1
// baseline (speedup 1.0000x reference)
#include <cuda_runtime.h>
#include <cuda_bf16.h>
#include <cstdint>

// Problem constants (from reference): BATCH=4096, IN=512, HID=16384, OUT=1000
#define B_BATCH 4096
#define K_IN    512
#define H_HID   16384
#define N_OUT   1000

// GEMM tiling
#define BM 128
#define BN 128
#define BK 16

// --------- device scratch (no allocations allowed) ----------
__device__ unsigned long long g_packed[B_BATCH];   // (monotone f32 key << 32) | col index
__device__ float g_w2[H_HID];                      // ||w_j||^2

// monotone mapping: float -> uint32 preserving order for unsigned compare
__device__ __forceinline__ unsigned int f32_key(float f) {
    unsigned int u = __float_as_uint(f);
    return u ^ ((u & 0x80000000u) ? 0xFFFFFFFFu : 0x80000000u);
}

// ---------------- kernel 1: row norms of kohonen weights ----------------
// one warp per row; 8 warps (8 rows) per block
__global__ void w2_kernel(const float* __restrict__ W) {
    int warp = threadIdx.x >> 5;
    int lane = threadIdx.x & 31;
    int row  = blockIdx.x * 8 + warp;
    const float4* p = reinterpret_cast<const float4*>(W + (size_t)row * K_IN);
    float s = 0.f;
    #pragma unroll
    for (int i = 0; i < 4; i++) {
        float4 v = p[lane + i * 32];
        s += v.x * v.x + v.y * v.y + v.z * v.z + v.w * v.w;
    }
    #pragma unroll
    for (int off = 16; off > 0; off >>= 1)
        s += __shfl_xor_sync(0xFFFFFFFFu, s, off);
    if (lane == 0) g_w2[row] = s;
}

// ---------------- kernel 2: init packed argmin scratch ----------------
__global__ void init_kernel() {
    int i = blockIdx.x * blockDim.x + threadIdx.x;
    if (i < B_BATCH) g_packed[i] = ~0ULL;
}

// ---------------- kernel 3: fused distance-score GEMM + argmin ----------------
// score[b][j] = w2[j] - 2 * dot(x[b], w[j])   (x2 + sqrt are monotone per-row, dropped)
__global__ __launch_bounds__(256, 2)
void dist_argmin_kernel(const float* __restrict__ X, const float* __restrict__ W) {
    __shared__ float As[BK][BM + 4];
    __shared__ float Bs[BK][BN + 4];
    __shared__ float w2s[BN];
    __shared__ unsigned long long smin[BM];

    const int tid  = threadIdx.x;
    const int row0 = blockIdx.y * BM;   // batch tile
    const int col0 = blockIdx.x * BN;   // hid tile

    if (tid < BN) w2s[tid] = g_w2[col0 + tid];
    if (tid < BM) smin[tid] = ~0ULL;

    const int tx = tid & 15;            // 0..15  (col group)
    const int ty = tid >> 4;            // 0..15  (row group)

    // global->shared load mapping: 4 threads per row, float4 each, 2 rows/thread
    const int lrow = tid >> 2;          // 0..63
    const int lk   = (tid & 3) * 4;     // 0,4,8,12

    float acc[8][8];
    #pragma unroll
    for (int i = 0; i < 8; i++)
        #pragma unroll
        for (int j = 0; j < 8; j++) acc[i][j] = 0.f;

    for (int k0 = 0; k0 < K_IN; k0 += BK) {
        #pragma unroll
        for (int r = 0; r < 2; r++) {
            int row = lrow + r * 64;
            float4 va = *reinterpret_cast<const float4*>(
                &X[(size_t)(row0 + row) * K_IN + k0 + lk]);
            As[lk + 0][row] = va.x; As[lk + 1][row] = va.y;
            As[lk + 2][row] = va.z; As[lk + 3][row] = va.w;
            float4 vb = *reinterpret_cast<const float4*>(
                &W[(size_t)(col0 + row) * K_IN + k0 + lk]);
            Bs[lk + 0][row] = vb.x; Bs[lk + 1][row] = vb.y;
            Bs[lk + 2][row] = vb.z; Bs[lk + 3][row] = vb.w;
        }
        __syncthreads();

        #pragma unroll
        for (int k = 0; k < BK; k++) {
            float a[8], b[8];
            #pragma unroll
            for (int i = 0; i < 8; i++) a[i] = As[k][ty * 8 + i];
            #pragma unroll
            for (int j = 0; j < 8; j++) b[j] = Bs[k][tx * 8 + j];
            #pragma unroll
            for (int i = 0; i < 8; i++)
                #pragma unroll
                for (int j = 0; j < 8; j++)
                    acc[i][j] = fmaf(a[i], b[j], acc[i][j]);
        }
        __syncthreads();
    }

    // per-thread min over its 8 columns for each of its 8 rows, then merge
    #pragma unroll
    for (int i = 0; i < 8; i++) {
        unsigned long long best = ~0ULL;
        #pragma unroll
        for (int j = 0; j < 8; j++) {
            int col = tx * 8 + j;
            float s = fmaf(-2.f, acc[i][j], w2s[col]);
            unsigned long long p =
                ((unsigned long long)f32_key(s) << 32) | (unsigned int)(col0 + col);
            best = best < p ? best : p;
        }
        atomicMin(&smin[ty * 8 + i], best);
    }
    __syncthreads();
    if (tid < BM) atomicMin(&g_packed[row0 + tid], smin[tid]);
}

// ---------------- kernel 4: gather grossberg columns + optional winners ----------------
__global__ void gather_kernel(const float* __restrict__ G, float* __restrict__ out,
                              int out_size) {
    int b = blockIdx.x;
    unsigned int w = (unsigned int)(g_packed[b] & 0xFFFFFFFFull);
    for (int o = threadIdx.x; o < N_OUT; o += blockDim.x)
        out[(size_t)b * N_OUT + o] = G[(size_t)o * H_HID + w];
    // if the flattened output tuple also contains winners, append as float
    if (threadIdx.x == 0 && out_size >= B_BATCH * N_OUT + B_BATCH)
        out[(size_t)B_BATCH * N_OUT + b] = (float)w;
}

// ---------------- launcher ----------------
extern "C" void kernel_launch(void* const* d_in, const int* in_sizes, int n_in,
                              void* d_out, int out_size) {
    const float* x  = (const float*)d_in[0];   // [4096, 512]
    const float* kw = (const float*)d_in[1];   // [16384, 512]
    const float* gw = (const float*)d_in[2];   // [1000, 16384]
    float* out = (float*)d_out;

    w2_kernel<<<H_HID / 8, 256>>>(kw);
    init_kernel<<<(B_BATCH + 255) / 256, 256>>>();

    dim3 grid(H_HID / BN, B_BATCH / BM);   // (128, 32): hid tiles fastest for L2 reuse
    dist_argmin_kernel<<<grid, 256>>>(x, kw);

    gather_kernel<<<B_BATCH, 256>>>(gw, out, out_size);
}

// round 5
// speedup vs baseline: 4.9747x; 4.9747x over previous
#include <cuda_runtime.h>
#include <cuda_fp16.h>
#include <cstdint>

// Problem constants: BATCH=4096, IN=512, HID=16384, OUT=1000
#define B_BATCH 4096
#define K_IN    512
#define H_HID   16384
#define N_OUT   1000

// Coarse GEMM tiling
#define BM 128
#define BN 256
#define BK 64
#define STAGES 3
#define THREADS 256
#define NCHUNK (K_IN / BK)   // 8

#define A_ST_BYTES (BM * BK * 2)              // 16384
#define B_ST_BYTES (BN * BK * 2)              // 32768
#define STAGE_BYTES (A_ST_BYTES + B_ST_BYTES) // 49152
#define GEMM_SMEM (STAGES * STAGE_BYTES)      // 147456

// Refine
#define CAP 1024
#define MARGIN 0.5f

// ---------------- device scratch (static; no allocs) ----------------
__device__ __half g_xh[(size_t)B_BATCH * K_IN];            // 4 MB
__device__ __half g_wh[(size_t)H_HID * K_IN];              // 16 MB
__device__ __half g_scores[(size_t)B_BATCH * H_HID];       // 128 MB
__device__ float g_w2[H_HID];
__device__ unsigned long long g_packed[B_BATCH];

// ---------------- helpers ----------------
__device__ __forceinline__ uint32_t smem_u32(const void* p) {
    uint32_t a;
    asm("{ .reg .u64 t; cvta.to.shared.u64 t, %1; cvt.u32.u64 %0, t; }" : "=r"(a) : "l"(p));
    return a;
}
__device__ __forceinline__ void cp_async16(uint32_t dst, const void* src) {
    asm volatile("cp.async.cg.shared.global [%0], [%1], 16;" :: "r"(dst), "l"(src) : "memory");
}
__device__ __forceinline__ void cp_commit() {
    asm volatile("cp.async.commit_group;" ::: "memory");
}
__device__ __forceinline__ void cp_wait1() {
    asm volatile("cp.async.wait_group 1;" ::: "memory");
}
__device__ __forceinline__ void cp_wait0() {
    asm volatile("cp.async.wait_group 0;" ::: "memory");
}
__device__ __forceinline__ void ldsm_x4(uint32_t* r, uint32_t addr) {
    asm volatile("ldmatrix.sync.aligned.m8n8.x4.shared.b16 {%0,%1,%2,%3}, [%4];"
                 : "=r"(r[0]), "=r"(r[1]), "=r"(r[2]), "=r"(r[3]) : "r"(addr));
}
__device__ __forceinline__ void mma16816(float* c, const uint32_t* a, const uint32_t* b) {
    asm volatile(
        "mma.sync.aligned.m16n8k16.row.col.f32.f16.f16.f32 "
        "{%0,%1,%2,%3}, {%4,%5,%6,%7}, {%8,%9}, {%0,%1,%2,%3};"
        : "+f"(c[0]), "+f"(c[1]), "+f"(c[2]), "+f"(c[3])
        : "r"(a[0]), "r"(a[1]), "r"(a[2]), "r"(a[3]), "r"(b[0]), "r"(b[1]));
}
__device__ __forceinline__ unsigned int f32_key(float f) {
    unsigned int u = __float_as_uint(f);
    return u ^ ((u & 0x80000000u) ? 0xFFFFFFFFu : 0x80000000u);
}

// ---------------- prep: fp16 convert (+ exact w2 for W) ----------------
// one warp per row, 8 warps/block
__global__ void prep_w_kernel(const float* __restrict__ W) {
    int warp = threadIdx.x >> 5, lane = threadIdx.x & 31;
    int row = blockIdx.x * 8 + warp;
    const float4* p = reinterpret_cast<const float4*>(W + (size_t)row * K_IN);
    uint2* dst = reinterpret_cast<uint2*>(g_wh + (size_t)row * K_IN);
    float s = 0.f;
    #pragma unroll
    for (int i = 0; i < 4; i++) {
        float4 v = p[lane + i * 32];
        s += v.x * v.x + v.y * v.y + v.z * v.z + v.w * v.w;
        __half2 h01 = __floats2half2_rn(v.x, v.y);
        __half2 h23 = __floats2half2_rn(v.z, v.w);
        uint2 u;
        u.x = *reinterpret_cast<uint32_t*>(&h01);
        u.y = *reinterpret_cast<uint32_t*>(&h23);
        dst[lane + i * 32] = u;
    }
    #pragma unroll
    for (int off = 16; off > 0; off >>= 1) s += __shfl_xor_sync(0xFFFFFFFFu, s, off);
    if (lane == 0) g_w2[row] = s;
}

__global__ void prep_x_kernel(const float* __restrict__ X) {
    int warp = threadIdx.x >> 5, lane = threadIdx.x & 31;
    int row = blockIdx.x * 8 + warp;
    const float4* p = reinterpret_cast<const float4*>(X + (size_t)row * K_IN);
    uint2* dst = reinterpret_cast<uint2*>(g_xh + (size_t)row * K_IN);
    #pragma unroll
    for (int i = 0; i < 4; i++) {
        float4 v = p[lane + i * 32];
        __half2 h01 = __floats2half2_rn(v.x, v.y);
        __half2 h23 = __floats2half2_rn(v.z, v.w);
        uint2 u;
        u.x = *reinterpret_cast<uint32_t*>(&h01);
        u.y = *reinterpret_cast<uint32_t*>(&h23);
        dst[lane + i * 32] = u;
    }
}

// ---------------- coarse GEMM: scores[b][j] = w2[j] - 2*dot_fp16(x,w) ----------------
__global__ void __launch_bounds__(THREADS, 1)
gemm_coarse_kernel() {
    extern __shared__ char smem[];
    __shared__ float w2s[BN];
    const uint32_t sb = smem_u32(smem);
    const int tid = threadIdx.x;
    const int row0 = blockIdx.x * BM;
    const int col0 = blockIdx.y * BN;

    for (int i = tid; i < BN; i += THREADS) w2s[i] = g_w2[col0 + i];

    const int lane = tid & 31, wid = tid >> 5;
    const int wm = wid >> 2, wn = wid & 3;   // 2 (M) x 4 (N) warps; warp tile 64x64

    // ---- async stage loader ----
    auto issue_stage = [&](int kc, int s) {
        uint32_t As = sb + s * STAGE_BYTES;
        uint32_t Bs = As + A_ST_BYTES;
        const __half* gA = g_xh + (size_t)row0 * K_IN + kc * BK;
        const __half* gB = g_wh + (size_t)col0 * K_IN + kc * BK;
        #pragma unroll
        for (int i = 0; i < 4; i++) {           // A: 128 rows x 8 chunks of 16B
            int id = tid + i * THREADS;
            int r = id >> 3, c = id & 7;
            cp_async16(As + r * 128 + ((c ^ (r & 7)) * 16), gA + (size_t)r * K_IN + c * 8);
        }
        #pragma unroll
        for (int i = 0; i < 8; i++) {           // B: 256 rows x 8 chunks of 16B
            int id = tid + i * THREADS;
            int r = id >> 3, c = id & 7;
            cp_async16(Bs + r * 128 + ((c ^ (r & 7)) * 16), gB + (size_t)r * K_IN + c * 8);
        }
        cp_commit();
    };

    float acc[4][8][4];
    #pragma unroll
    for (int i = 0; i < 4; i++)
        #pragma unroll
        for (int j = 0; j < 8; j++)
            #pragma unroll
            for (int c = 0; c < 4; c++) acc[i][j][c] = 0.f;

    issue_stage(0, 0);
    issue_stage(1, 1);

    for (int ki = 0; ki < NCHUNK; ki++) {
        if (ki == NCHUNK - 1) cp_wait0(); else cp_wait1();
        __syncthreads();
        if (ki + 2 < NCHUNK) issue_stage(ki + 2, (ki + 2) % STAGES);

        uint32_t As = sb + (ki % STAGES) * STAGE_BYTES;
        uint32_t Bs = As + A_ST_BYTES;

        #pragma unroll
        for (int kk = 0; kk < 4; kk++) {        // 4 x k16 per chunk
            uint32_t afr[4][4];
            #pragma unroll
            for (int mi = 0; mi < 4; mi++) {
                int row = wm * 64 + mi * 16 + (lane & 15);
                int kc8 = kk * 2 + (lane >> 4);
                ldsm_x4(afr[mi], As + row * 128 + ((kc8 ^ (row & 7)) * 16));
            }
            uint32_t bfr[8][2];
            #pragma unroll
            for (int p = 0; p < 4; p++) {       // each x4 covers 2 n8-tiles
                int n   = wn * 64 + p * 16 + (lane >> 4) * 8 + (lane & 7);
                int kc8 = kk * 2 + ((lane >> 3) & 1);
                uint32_t r[4];
                ldsm_x4(r, Bs + n * 128 + ((kc8 ^ (n & 7)) * 16));
                bfr[2 * p][0] = r[0]; bfr[2 * p][1] = r[1];
                bfr[2 * p + 1][0] = r[2]; bfr[2 * p + 1][1] = r[3];
            }
            #pragma unroll
            for (int mi = 0; mi < 4; mi++)
                #pragma unroll
                for (int nj = 0; nj < 8; nj++)
                    mma16816(acc[mi][nj], afr[mi], bfr[nj]);
        }
    }

    // ---- epilogue: score = w2 - 2*dot, store fp16 ----
    const int qr = lane >> 2, qc = lane & 3;
    #pragma unroll
    for (int mi = 0; mi < 4; mi++) {
        #pragma unroll
        for (int h = 0; h < 2; h++) {
            int r = row0 + wm * 64 + mi * 16 + qr + h * 8;
            __half* orow = g_scores + (size_t)r * H_HID;
            #pragma unroll
            for (int nj = 0; nj < 8; nj++) {
                int cl = wn * 64 + nj * 8 + 2 * qc;
                float s0 = fmaf(-2.f, acc[mi][nj][h * 2 + 0], w2s[cl]);
                float s1 = fmaf(-2.f, acc[mi][nj][h * 2 + 1], w2s[cl + 1]);
                __half2 hv = __floats2half2_rn(s0, s1);
                *reinterpret_cast<__half2*>(orow + col0 + cl) = hv;
            }
        }
    }
}

// ---------------- refine: exact fp32 re-score of coarse candidates ----------------
__global__ void __launch_bounds__(256)
refine_kernel(const float* __restrict__ X, const float* __restrict__ W) {
    __shared__ float s_min[8];
    __shared__ int s_cand[CAP];
    __shared__ int s_cnt;
    __shared__ unsigned long long s_best;
    const int b = blockIdx.x, tid = threadIdx.x;
    const int lane = tid & 31, wid = tid >> 5;

    const __half2* sc = reinterpret_cast<const __half2*>(g_scores + (size_t)b * H_HID);
    float mn = 1e30f;
    for (int j = tid; j < H_HID / 2; j += 256) {
        float2 v = __half22float2(sc[j]);
        mn = fminf(mn, fminf(v.x, v.y));
    }
    #pragma unroll
    for (int o = 16; o > 0; o >>= 1) mn = fminf(mn, __shfl_xor_sync(0xFFFFFFFFu, mn, o));
    if (lane == 0) s_min[wid] = mn;
    if (tid == 0) { s_cnt = 0; s_best = ~0ULL; }
    __syncthreads();
    if (tid == 0) {
        float m = s_min[0];
        #pragma unroll
        for (int i = 1; i < 8; i++) m = fminf(m, s_min[i]);
        s_min[0] = m;
    }
    __syncthreads();
    const float thr = s_min[0] + MARGIN;

    for (int j = tid; j < H_HID / 2; j += 256) {
        float2 v = __half22float2(sc[j]);
        if (v.x <= thr) { int p = atomicAdd(&s_cnt, 1); if (p < CAP) s_cand[p] = 2 * j; }
        if (v.y <= thr) { int p = atomicAdd(&s_cnt, 1); if (p < CAP) s_cand[p] = 2 * j + 1; }
    }
    __syncthreads();
    const int cnt = min(s_cnt, CAP);
    const float4* x4 = reinterpret_cast<const float4*>(X + (size_t)b * K_IN);
    for (int c = wid; c < cnt; c += 8) {
        int j = s_cand[c];
        const float4* w4 = reinterpret_cast<const float4*>(W + (size_t)j * K_IN);
        float acc = 0.f;
        #pragma unroll
        for (int i = 0; i < 4; i++) {
            float4 a = x4[lane + i * 32], w = w4[lane + i * 32];
            acc += a.x * w.x + a.y * w.y + a.z * w.z + a.w * w.w;
        }
        #pragma unroll
        for (int o = 16; o > 0; o >>= 1) acc += __shfl_xor_sync(0xFFFFFFFFu, acc, o);
        if (lane == 0) {
            float s = fmaf(-2.f, acc, g_w2[j]);
            unsigned long long p =
                ((unsigned long long)f32_key(s) << 32) | (unsigned int)j;
            atomicMin(&s_best, p);
        }
    }
    __syncthreads();
    if (tid == 0) g_packed[b] = s_best;
}

// ---------------- gather grossberg columns ----------------
__global__ void gather_kernel(const float* __restrict__ G, float* __restrict__ out,
                              int out_size) {
    int b = blockIdx.x;
    unsigned int w = (unsigned int)(g_packed[b] & 0xFFFFFFFFull);
    for (int o = threadIdx.x; o < N_OUT; o += blockDim.x)
        out[(size_t)b * N_OUT + o] = G[(size_t)o * H_HID + w];
    if (threadIdx.x == 0 && out_size >= B_BATCH * N_OUT + B_BATCH)
        out[(size_t)B_BATCH * N_OUT + b] = (float)w;
}

// ---------------- launcher ----------------
extern "C" void kernel_launch(void* const* d_in, const int* in_sizes, int n_in,
                              void* d_out, int out_size) {
    const float* x  = (const float*)d_in[0];   // [4096, 512]
    const float* kw = (const float*)d_in[1];   // [16384, 512]
    const float* gw = (const float*)d_in[2];   // [1000, 16384]
    float* out = (float*)d_out;

    cudaFuncSetAttribute(gemm_coarse_kernel,
                         cudaFuncAttributeMaxDynamicSharedMemorySize, GEMM_SMEM);

    prep_x_kernel<<<B_BATCH / 8, 256>>>(x);
    prep_w_kernel<<<H_HID / 8, 256>>>(kw);

    dim3 grid(B_BATCH / BM, H_HID / BN);   // (32, 64)
    gemm_coarse_kernel<<<grid, THREADS, GEMM_SMEM>>>();

    refine_kernel<<<B_BATCH, 256>>>(x, kw);
    gather_kernel<<<B_BATCH, 256>>>(gw, out, out_size);
}

// round 6
// speedup vs baseline: 7.3356x; 1.4746x over previous
#include <cuda_runtime.h>
#include <cuda_fp16.h>
#include <cstdint>

// Problem constants: BATCH=4096, IN=512, HID=16384, OUT=1000
#define B_BATCH 4096
#define K_IN    512
#define H_HID   16384
#define N_OUT   1000

// Coarse GEMM tiling (int8): BK=128 int8 = 128B rows (same smem geometry as fp16 BK=64)
#define BM 128
#define BN 256
#define BK 128
#define STAGES 3
#define THREADS 256
#define NCHUNK (K_IN / BK)   // 4

#define A_ST_BYTES (BM * BK)                  // 16384
#define B_ST_BYTES (BN * BK)                  // 32768
#define STAGE_BYTES (A_ST_BYTES + B_ST_BYTES) // 49152
#define GEMM_SMEM (STAGES * STAGE_BYTES)      // 147456

// Refine
#define CAP 1024
#define MARGIN 0.5f

// ---------------- device scratch (static; no allocs) ----------------
__device__ int8_t g_xq[(size_t)B_BATCH * K_IN];            // 2 MB
__device__ int8_t g_wq[(size_t)H_HID * K_IN];              // 8 MB
__device__ float  g_dx[B_BATCH];                           // x dequant scale per row
__device__ float  g_dw[H_HID];                             // w dequant scale per row
__device__ __half g_scores[(size_t)B_BATCH * H_HID];       // 128 MB
__device__ float  g_w2[H_HID];
__device__ unsigned long long g_packed[B_BATCH];

// ---------------- helpers ----------------
__device__ __forceinline__ uint32_t smem_u32(const void* p) {
    uint32_t a;
    asm("{ .reg .u64 t; cvta.to.shared.u64 t, %1; cvt.u32.u64 %0, t; }" : "=r"(a) : "l"(p));
    return a;
}
__device__ __forceinline__ void cp_async16(uint32_t dst, const void* src) {
    asm volatile("cp.async.cg.shared.global [%0], [%1], 16;" :: "r"(dst), "l"(src) : "memory");
}
__device__ __forceinline__ void cp_commit() {
    asm volatile("cp.async.commit_group;" ::: "memory");
}
__device__ __forceinline__ void cp_wait1() {
    asm volatile("cp.async.wait_group 1;" ::: "memory");
}
__device__ __forceinline__ void cp_wait0() {
    asm volatile("cp.async.wait_group 0;" ::: "memory");
}
__device__ __forceinline__ void ldsm_x4(uint32_t* r, uint32_t addr) {
    asm volatile("ldmatrix.sync.aligned.m8n8.x4.shared.b16 {%0,%1,%2,%3}, [%4];"
                 : "=r"(r[0]), "=r"(r[1]), "=r"(r[2]), "=r"(r[3]) : "r"(addr));
}
// s8 x s8 -> s32, m16n8k32 (fragment-isomorphic to f16 m16n8k16 with 2 bytes per slot)
__device__ __forceinline__ void mma16832s8(int* c, const uint32_t* a, const uint32_t* b) {
    asm volatile(
        "mma.sync.aligned.m16n8k32.row.col.s32.s8.s8.s32 "
        "{%0,%1,%2,%3}, {%4,%5,%6,%7}, {%8,%9}, {%0,%1,%2,%3};"
        : "+r"(c[0]), "+r"(c[1]), "+r"(c[2]), "+r"(c[3])
        : "r"(a[0]), "r"(a[1]), "r"(a[2]), "r"(a[3]), "r"(b[0]), "r"(b[1]));
}
__device__ __forceinline__ unsigned int f32_key(float f) {
    unsigned int u = __float_as_uint(f);
    return u ^ ((u & 0x80000000u) ? 0xFFFFFFFFu : 0x80000000u);
}
__device__ __forceinline__ uint32_t pack4(float a, float b, float c, float d, float sx) {
    int ia = __float2int_rn(fminf(fmaxf(a * sx, -127.f), 127.f));
    int ib = __float2int_rn(fminf(fmaxf(b * sx, -127.f), 127.f));
    int ic = __float2int_rn(fminf(fmaxf(c * sx, -127.f), 127.f));
    int id = __float2int_rn(fminf(fmaxf(d * sx, -127.f), 127.f));
    return (ia & 0xFF) | ((ib & 0xFF) << 8) | ((ic & 0xFF) << 16) | ((id & 0xFF) << 24);
}

// ---------------- prep: int8 quantize per row (+ exact w2 for W) ----------------
// one warp per row, 8 warps/block
__global__ void prep_w_kernel(const float* __restrict__ W) {
    int warp = threadIdx.x >> 5, lane = threadIdx.x & 31;
    int row = blockIdx.x * 8 + warp;
    const float4* p = reinterpret_cast<const float4*>(W + (size_t)row * K_IN);
    float4 v[4];
    float s = 0.f, mx = 0.f;
    #pragma unroll
    for (int i = 0; i < 4; i++) {
        v[i] = p[lane + i * 32];
        s += v[i].x * v[i].x + v[i].y * v[i].y + v[i].z * v[i].z + v[i].w * v[i].w;
        mx = fmaxf(mx, fmaxf(fmaxf(fabsf(v[i].x), fabsf(v[i].y)),
                             fmaxf(fabsf(v[i].z), fabsf(v[i].w))));
    }
    #pragma unroll
    for (int off = 16; off > 0; off >>= 1) {
        s += __shfl_xor_sync(0xFFFFFFFFu, s, off);
        mx = fmaxf(mx, __shfl_xor_sync(0xFFFFFFFFu, mx, off));
    }
    mx = fmaxf(mx, 1e-20f);
    float sx = 127.f / mx;
    uint32_t* dst = reinterpret_cast<uint32_t*>(g_wq + (size_t)row * K_IN);
    #pragma unroll
    for (int i = 0; i < 4; i++)
        dst[lane + i * 32] = pack4(v[i].x, v[i].y, v[i].z, v[i].w, sx);
    if (lane == 0) { g_w2[row] = s; g_dw[row] = mx / 127.f; }
}

__global__ void prep_x_kernel(const float* __restrict__ X) {
    int warp = threadIdx.x >> 5, lane = threadIdx.x & 31;
    int row = blockIdx.x * 8 + warp;
    const float4* p = reinterpret_cast<const float4*>(X + (size_t)row * K_IN);
    float4 v[4];
    float mx = 0.f;
    #pragma unroll
    for (int i = 0; i < 4; i++) {
        v[i] = p[lane + i * 32];
        mx = fmaxf(mx, fmaxf(fmaxf(fabsf(v[i].x), fabsf(v[i].y)),
                             fmaxf(fabsf(v[i].z), fabsf(v[i].w))));
    }
    #pragma unroll
    for (int off = 16; off > 0; off >>= 1)
        mx = fmaxf(mx, __shfl_xor_sync(0xFFFFFFFFu, mx, off));
    mx = fmaxf(mx, 1e-20f);
    float sx = 127.f / mx;
    uint32_t* dst = reinterpret_cast<uint32_t*>(g_xq + (size_t)row * K_IN);
    #pragma unroll
    for (int i = 0; i < 4; i++)
        dst[lane + i * 32] = pack4(v[i].x, v[i].y, v[i].z, v[i].w, sx);
    if (lane == 0) g_dx[row] = mx / 127.f;
}

// ---------------- coarse GEMM (int8): scores[b][j] = w2[j] - 2*dx*dw*dot_int ----------------
__global__ void __launch_bounds__(THREADS, 1)
gemm_coarse_kernel() {
    extern __shared__ char smem[];
    __shared__ float w2s[BN];
    __shared__ float dws[BN];
    __shared__ float dxs[BM];
    const uint32_t sb = smem_u32(smem);
    const int tid = threadIdx.x;
    const int row0 = blockIdx.x * BM;
    const int col0 = blockIdx.y * BN;

    for (int i = tid; i < BN; i += THREADS) { w2s[i] = g_w2[col0 + i]; dws[i] = g_dw[col0 + i]; }
    if (tid < BM) dxs[tid] = g_dx[row0 + tid];

    const int lane = tid & 31, wid = tid >> 5;
    const int wm = wid >> 2, wn = wid & 3;   // 2 (M) x 4 (N) warps; warp tile 64x64

    // ---- async stage loader (identical byte-geometry to validated fp16 version) ----
    auto issue_stage = [&](int kc, int s) {
        uint32_t As = sb + s * STAGE_BYTES;
        uint32_t Bs = As + A_ST_BYTES;
        const int8_t* gA = g_xq + (size_t)row0 * K_IN + kc * BK;
        const int8_t* gB = g_wq + (size_t)col0 * K_IN + kc * BK;
        #pragma unroll
        for (int i = 0; i < 4; i++) {           // A: 128 rows x 8 chunks of 16B
            int id = tid + i * THREADS;
            int r = id >> 3, c = id & 7;
            cp_async16(As + r * 128 + ((c ^ (r & 7)) * 16), gA + (size_t)r * K_IN + c * 16);
        }
        #pragma unroll
        for (int i = 0; i < 8; i++) {           // B: 256 rows x 8 chunks of 16B
            int id = tid + i * THREADS;
            int r = id >> 3, c = id & 7;
            cp_async16(Bs + r * 128 + ((c ^ (r & 7)) * 16), gB + (size_t)r * K_IN + c * 16);
        }
        cp_commit();
    };

    int acc[4][8][4];
    #pragma unroll
    for (int i = 0; i < 4; i++)
        #pragma unroll
        for (int j = 0; j < 8; j++)
            #pragma unroll
            for (int c = 0; c < 4; c++) acc[i][j][c] = 0;

    issue_stage(0, 0);
    issue_stage(1, 1);

    for (int ki = 0; ki < NCHUNK; ki++) {
        if (ki == NCHUNK - 1) cp_wait0(); else cp_wait1();
        __syncthreads();
        if (ki + 2 < NCHUNK) issue_stage(ki + 2, (ki + 2) % STAGES);

        uint32_t As = sb + (ki % STAGES) * STAGE_BYTES;
        uint32_t Bs = As + A_ST_BYTES;

        #pragma unroll
        for (int kk = 0; kk < 4; kk++) {        // 4 x k32 per 128B chunk
            uint32_t afr[4][4];
            #pragma unroll
            for (int mi = 0; mi < 4; mi++) {
                int row = wm * 64 + mi * 16 + (lane & 15);
                int kc = kk * 2 + (lane >> 4);
                ldsm_x4(afr[mi], As + row * 128 + ((kc ^ (row & 7)) * 16));
            }
            uint32_t bfr[8][2];
            #pragma unroll
            for (int p = 0; p < 4; p++) {       // each x4 covers 2 n8-tiles
                int n  = wn * 64 + p * 16 + (lane >> 4) * 8 + (lane & 7);
                int kc = kk * 2 + ((lane >> 3) & 1);
                uint32_t r[4];
                ldsm_x4(r, Bs + n * 128 + ((kc ^ (n & 7)) * 16));
                bfr[2 * p][0] = r[0]; bfr[2 * p][1] = r[1];
                bfr[2 * p + 1][0] = r[2]; bfr[2 * p + 1][1] = r[3];
            }
            #pragma unroll
            for (int mi = 0; mi < 4; mi++)
                #pragma unroll
                for (int nj = 0; nj < 8; nj++)
                    mma16832s8(acc[mi][nj], afr[mi], bfr[nj]);
        }
    }

    // ---- epilogue: score = w2 - 2*dx*dw*dot_int, store fp16 ----
    const int qr = lane >> 2, qc = lane & 3;
    #pragma unroll
    for (int mi = 0; mi < 4; mi++) {
        #pragma unroll
        for (int h = 0; h < 2; h++) {
            int lrow = wm * 64 + mi * 16 + qr + h * 8;
            float ndx2 = -2.f * dxs[lrow];
            __half* orow = g_scores + (size_t)(row0 + lrow) * H_HID;
            #pragma unroll
            for (int nj = 0; nj < 8; nj++) {
                int cl = wn * 64 + nj * 8 + 2 * qc;
                float s0 = fmaf(ndx2 * dws[cl],     (float)acc[mi][nj][h * 2 + 0], w2s[cl]);
                float s1 = fmaf(ndx2 * dws[cl + 1], (float)acc[mi][nj][h * 2 + 1], w2s[cl + 1]);
                __half2 hv = __floats2half2_rn(s0, s1);
                *reinterpret_cast<__half2*>(orow + col0 + cl) = hv;
            }
        }
    }
}

// ---------------- refine: single-pass scan + exact fp32 re-score ----------------
#define NGRP (H_HID / 8)   // 2048 groups of 8 halves (16B)
__global__ void __launch_bounds__(256)
refine_kernel(const float* __restrict__ X, const float* __restrict__ W) {
    __shared__ __half s_gm[NGRP];    // per-16B-group minima
    __shared__ float s_min[8];
    __shared__ int s_cand[CAP];
    __shared__ int s_cnt;
    __shared__ unsigned long long s_best;
    const int b = blockIdx.x, tid = threadIdx.x;
    const int lane = tid & 31, wid = tid >> 5;

    const int4* sc = reinterpret_cast<const int4*>(g_scores + (size_t)b * H_HID);
    float mn = 1e30f;
    #pragma unroll
    for (int i = 0; i < NGRP / 256; i++) {       // 8 iterations, single DRAM pass
        int g = tid + i * 256;
        int4 q = sc[g];
        __half2 h0 = *reinterpret_cast<__half2*>(&q.x);
        __half2 h1 = *reinterpret_cast<__half2*>(&q.y);
        __half2 h2 = *reinterpret_cast<__half2*>(&q.z);
        __half2 h3 = *reinterpret_cast<__half2*>(&q.w);
        __half2 m01 = __hmin2(h0, h1), m23 = __hmin2(h2, h3);
        __half2 m = __hmin2(m01, m23);
        __half gmin = __hmin(__low2half(m), __high2half(m));
        s_gm[g] = gmin;
        mn = fminf(mn, __half2float(gmin));
    }
    #pragma unroll
    for (int o = 16; o > 0; o >>= 1) mn = fminf(mn, __shfl_xor_sync(0xFFFFFFFFu, mn, o));
    if (lane == 0) s_min[wid] = mn;
    if (tid == 0) { s_cnt = 0; s_best = ~0ULL; }
    __syncthreads();
    if (tid == 0) {
        float m = s_min[0];
        #pragma unroll
        for (int i = 1; i < 8; i++) m = fminf(m, s_min[i]);
        s_min[0] = m;
    }
    __syncthreads();
    const float thr = s_min[0] + MARGIN;

    // pass 2: only re-touch qualifying groups (row is L2-resident)
    #pragma unroll
    for (int i = 0; i < NGRP / 256; i++) {
        int g = tid + i * 256;
        if (__half2float(s_gm[g]) <= thr) {
            int4 q = sc[g];
            const __half* hp = reinterpret_cast<const __half*>(&q);
            #pragma unroll
            for (int e = 0; e < 8; e++) {
                if (__half2float(hp[e]) <= thr) {
                    int p = atomicAdd(&s_cnt, 1);
                    if (p < CAP) s_cand[p] = g * 8 + e;
                }
            }
        }
    }
    __syncthreads();
    const int cnt = min(s_cnt, CAP);
    const float4* x4 = reinterpret_cast<const float4*>(X + (size_t)b * K_IN);
    for (int c = wid; c < cnt; c += 8) {
        int j = s_cand[c];
        const float4* w4 = reinterpret_cast<const float4*>(W + (size_t)j * K_IN);
        float acc = 0.f;
        #pragma unroll
        for (int i = 0; i < 4; i++) {
            float4 a = x4[lane + i * 32], w = w4[lane + i * 32];
            acc += a.x * w.x + a.y * w.y + a.z * w.z + a.w * w.w;
        }
        #pragma unroll
        for (int o = 16; o > 0; o >>= 1) acc += __shfl_xor_sync(0xFFFFFFFFu, acc, o);
        if (lane == 0) {
            float s = fmaf(-2.f, acc, g_w2[j]);
            unsigned long long p =
                ((unsigned long long)f32_key(s) << 32) | (unsigned int)j;
            atomicMin(&s_best, p);
        }
    }
    __syncthreads();
    if (tid == 0) g_packed[b] = s_best;
}

// ---------------- gather grossberg columns ----------------
__global__ void gather_kernel(const float* __restrict__ G, float* __restrict__ out,
                              int out_size) {
    int b = blockIdx.x;
    unsigned int w = (unsigned int)(g_packed[b] & 0xFFFFFFFFull);
    for (int o = threadIdx.x; o < N_OUT; o += blockDim.x)
        out[(size_t)b * N_OUT + o] = G[(size_t)o * H_HID + w];
    if (threadIdx.x == 0 && out_size >= B_BATCH * N_OUT + B_BATCH)
        out[(size_t)B_BATCH * N_OUT + b] = (float)w;
}

// ---------------- launcher ----------------
extern "C" void kernel_launch(void* const* d_in, const int* in_sizes, int n_in,
                              void* d_out, int out_size) {
    const float* x  = (const float*)d_in[0];   // [4096, 512]
    const float* kw = (const float*)d_in[1];   // [16384, 512]
    const float* gw = (const float*)d_in[2];   // [1000, 16384]
    float* out = (float*)d_out;

    cudaFuncSetAttribute(gemm_coarse_kernel,
                         cudaFuncAttributeMaxDynamicSharedMemorySize, GEMM_SMEM);

    prep_x_kernel<<<B_BATCH / 8, 256>>>(x);
    prep_w_kernel<<<H_HID / 8, 256>>>(kw);

    dim3 grid(B_BATCH / BM, H_HID / BN);   // (32, 64)
    gemm_coarse_kernel<<<grid, THREADS, GEMM_SMEM>>>();

    refine_kernel<<<B_BATCH, 256>>>(x, kw);
    gather_kernel<<<B_BATCH, 256>>>(gw, out, out_size);
}

// round 7
// speedup vs baseline: 8.9205x; 1.2160x over previous
#include <cuda_runtime.h>
#include <cuda_fp16.h>
#include <cstdint>

// Problem constants: BATCH=4096, IN=512, HID=16384, OUT=1000
#define B_BATCH 4096
#define K_IN    512
#define H_HID   16384
#define N_OUT   1000

// Coarse GEMM tiling (int8): BK=128 int8 = 128B rows
#define BM 128
#define BN 256
#define BK 128
#define STAGES 3
#define THREADS 256
#define NCHUNK (K_IN / BK)   // 4

#define A_ST_BYTES (BM * BK)                  // 16384
#define B_ST_BYTES (BN * BK)                  // 32768
#define STAGE_BYTES (A_ST_BYTES + B_ST_BYTES) // 49152
#define GEMM_SMEM (STAGES * STAGE_BYTES)      // 147456

#define NGRP (H_HID / 8)     // 2048 groups of 8 columns per batch row
#define MARGIN 0.5f

// ---------------- device scratch (static; no allocs) ----------------
__device__ int8_t g_xq[(size_t)B_BATCH * K_IN];            // 2 MB
__device__ int8_t g_wq[(size_t)H_HID * K_IN];              // 8 MB
__device__ float  g_dx[B_BATCH];
__device__ float  g_dw[H_HID];
__device__ __half g_gmin[(size_t)B_BATCH * NGRP];          // 16 MB: per-8col group minima
__device__ float  g_w2[H_HID];
__device__ unsigned long long g_packed[B_BATCH];

// ---------------- helpers ----------------
__device__ __forceinline__ uint32_t smem_u32(const void* p) {
    uint32_t a;
    asm("{ .reg .u64 t; cvta.to.shared.u64 t, %1; cvt.u32.u64 %0, t; }" : "=r"(a) : "l"(p));
    return a;
}
__device__ __forceinline__ void cp_async16(uint32_t dst, const void* src) {
    asm volatile("cp.async.cg.shared.global [%0], [%1], 16;" :: "r"(dst), "l"(src) : "memory");
}
__device__ __forceinline__ void cp_commit() {
    asm volatile("cp.async.commit_group;" ::: "memory");
}
__device__ __forceinline__ void cp_wait1() {
    asm volatile("cp.async.wait_group 1;" ::: "memory");
}
__device__ __forceinline__ void cp_wait0() {
    asm volatile("cp.async.wait_group 0;" ::: "memory");
}
__device__ __forceinline__ void ldsm_x4(uint32_t* r, uint32_t addr) {
    asm volatile("ldmatrix.sync.aligned.m8n8.x4.shared.b16 {%0,%1,%2,%3}, [%4];"
                 : "=r"(r[0]), "=r"(r[1]), "=r"(r[2]), "=r"(r[3]) : "r"(addr));
}
__device__ __forceinline__ void mma16832s8(int* c, const uint32_t* a, const uint32_t* b) {
    asm volatile(
        "mma.sync.aligned.m16n8k32.row.col.s32.s8.s8.s32 "
        "{%0,%1,%2,%3}, {%4,%5,%6,%7}, {%8,%9}, {%0,%1,%2,%3};"
        : "+r"(c[0]), "+r"(c[1]), "+r"(c[2]), "+r"(c[3])
        : "r"(a[0]), "r"(a[1]), "r"(a[2]), "r"(a[3]), "r"(b[0]), "r"(b[1]));
}
__device__ __forceinline__ unsigned int f32_key(float f) {
    unsigned int u = __float_as_uint(f);
    return u ^ ((u & 0x80000000u) ? 0xFFFFFFFFu : 0x80000000u);
}
__device__ __forceinline__ uint32_t pack4(float a, float b, float c, float d, float sx) {
    int ia = __float2int_rn(fminf(fmaxf(a * sx, -127.f), 127.f));
    int ib = __float2int_rn(fminf(fmaxf(b * sx, -127.f), 127.f));
    int ic = __float2int_rn(fminf(fmaxf(c * sx, -127.f), 127.f));
    int id = __float2int_rn(fminf(fmaxf(d * sx, -127.f), 127.f));
    return (ia & 0xFF) | ((ib & 0xFF) << 8) | ((ic & 0xFF) << 16) | ((id & 0xFF) << 24);
}

// ---------------- prep: int8 quantize per row (+ exact w2 for W) ----------------
__global__ void prep_w_kernel(const float* __restrict__ W) {
    int warp = threadIdx.x >> 5, lane = threadIdx.x & 31;
    int row = blockIdx.x * 8 + warp;
    const float4* p = reinterpret_cast<const float4*>(W + (size_t)row * K_IN);
    float4 v[4];
    float s = 0.f, mx = 0.f;
    #pragma unroll
    for (int i = 0; i < 4; i++) {
        v[i] = p[lane + i * 32];
        s += v[i].x * v[i].x + v[i].y * v[i].y + v[i].z * v[i].z + v[i].w * v[i].w;
        mx = fmaxf(mx, fmaxf(fmaxf(fabsf(v[i].x), fabsf(v[i].y)),
                             fmaxf(fabsf(v[i].z), fabsf(v[i].w))));
    }
    #pragma unroll
    for (int off = 16; off > 0; off >>= 1) {
        s += __shfl_xor_sync(0xFFFFFFFFu, s, off);
        mx = fmaxf(mx, __shfl_xor_sync(0xFFFFFFFFu, mx, off));
    }
    mx = fmaxf(mx, 1e-20f);
    float sx = 127.f / mx;
    uint32_t* dst = reinterpret_cast<uint32_t*>(g_wq + (size_t)row * K_IN);
    #pragma unroll
    for (int i = 0; i < 4; i++)
        dst[lane + i * 32] = pack4(v[i].x, v[i].y, v[i].z, v[i].w, sx);
    if (lane == 0) { g_w2[row] = s; g_dw[row] = mx / 127.f; }
}

__global__ void prep_x_kernel(const float* __restrict__ X) {
    int warp = threadIdx.x >> 5, lane = threadIdx.x & 31;
    int row = blockIdx.x * 8 + warp;
    const float4* p = reinterpret_cast<const float4*>(X + (size_t)row * K_IN);
    float4 v[4];
    float mx = 0.f;
    #pragma unroll
    for (int i = 0; i < 4; i++) {
        v[i] = p[lane + i * 32];
        mx = fmaxf(mx, fmaxf(fmaxf(fabsf(v[i].x), fabsf(v[i].y)),
                             fmaxf(fabsf(v[i].z), fabsf(v[i].w))));
    }
    #pragma unroll
    for (int off = 16; off > 0; off >>= 1)
        mx = fmaxf(mx, __shfl_xor_sync(0xFFFFFFFFu, mx, off));
    mx = fmaxf(mx, 1e-20f);
    float sx = 127.f / mx;
    uint32_t* dst = reinterpret_cast<uint32_t*>(g_xq + (size_t)row * K_IN);
    #pragma unroll
    for (int i = 0; i < 4; i++)
        dst[lane + i * 32] = pack4(v[i].x, v[i].y, v[i].z, v[i].w, sx);
    if (lane == 0) g_dx[row] = mx / 127.f;
}

// ---------------- coarse GEMM (int8) with fused per-8col group-min epilogue ----------------
__global__ void __launch_bounds__(THREADS, 1)
gemm_coarse_kernel() {
    extern __shared__ char smem[];
    __shared__ float w2s[BN];
    __shared__ float dws[BN];
    __shared__ float dxs[BM];
    const uint32_t sb = smem_u32(smem);
    const int tid = threadIdx.x;
    const int row0 = blockIdx.x * BM;
    const int col0 = blockIdx.y * BN;

    for (int i = tid; i < BN; i += THREADS) { w2s[i] = g_w2[col0 + i]; dws[i] = g_dw[col0 + i]; }
    if (tid < BM) dxs[tid] = g_dx[row0 + tid];

    const int lane = tid & 31, wid = tid >> 5;
    const int wm = wid >> 2, wn = wid & 3;   // 2 (M) x 4 (N) warps; warp tile 64x64

    auto issue_stage = [&](int kc, int s) {
        uint32_t As = sb + s * STAGE_BYTES;
        uint32_t Bs = As + A_ST_BYTES;
        const int8_t* gA = g_xq + (size_t)row0 * K_IN + kc * BK;
        const int8_t* gB = g_wq + (size_t)col0 * K_IN + kc * BK;
        #pragma unroll
        for (int i = 0; i < 4; i++) {           // A: 128 rows x 8 chunks of 16B
            int id = tid + i * THREADS;
            int r = id >> 3, c = id & 7;
            cp_async16(As + r * 128 + ((c ^ (r & 7)) * 16), gA + (size_t)r * K_IN + c * 16);
        }
        #pragma unroll
        for (int i = 0; i < 8; i++) {           // B: 256 rows x 8 chunks of 16B
            int id = tid + i * THREADS;
            int r = id >> 3, c = id & 7;
            cp_async16(Bs + r * 128 + ((c ^ (r & 7)) * 16), gB + (size_t)r * K_IN + c * 16);
        }
        cp_commit();
    };

    int acc[4][8][4];
    #pragma unroll
    for (int i = 0; i < 4; i++)
        #pragma unroll
        for (int j = 0; j < 8; j++)
            #pragma unroll
            for (int c = 0; c < 4; c++) acc[i][j][c] = 0;

    issue_stage(0, 0);
    issue_stage(1, 1);

    for (int ki = 0; ki < NCHUNK; ki++) {
        if (ki == NCHUNK - 1) cp_wait0(); else cp_wait1();
        __syncthreads();
        if (ki + 2 < NCHUNK) issue_stage(ki + 2, (ki + 2) % STAGES);

        uint32_t As = sb + (ki % STAGES) * STAGE_BYTES;
        uint32_t Bs = As + A_ST_BYTES;

        #pragma unroll
        for (int kk = 0; kk < 4; kk++) {        // 4 x k32 per 128B chunk
            uint32_t afr[4][4];
            #pragma unroll
            for (int mi = 0; mi < 4; mi++) {
                int row = wm * 64 + mi * 16 + (lane & 15);
                int kc = kk * 2 + (lane >> 4);
                ldsm_x4(afr[mi], As + row * 128 + ((kc ^ (row & 7)) * 16));
            }
            uint32_t bfr[8][2];
            #pragma unroll
            for (int p = 0; p < 4; p++) {
                int n  = wn * 64 + p * 16 + (lane >> 4) * 8 + (lane & 7);
                int kc = kk * 2 + ((lane >> 3) & 1);
                uint32_t r[4];
                ldsm_x4(r, Bs + n * 128 + ((kc ^ (n & 7)) * 16));
                bfr[2 * p][0] = r[0]; bfr[2 * p][1] = r[1];
                bfr[2 * p + 1][0] = r[2]; bfr[2 * p + 1][1] = r[3];
            }
            #pragma unroll
            for (int mi = 0; mi < 4; mi++)
                #pragma unroll
                for (int nj = 0; nj < 8; nj++)
                    mma16832s8(acc[mi][nj], afr[mi], bfr[nj]);
        }
    }

    // ---- epilogue: score = w2 - 2*dx*dw*dot; quad-reduce to per-8col group min ----
    const int qr = lane >> 2, qc = lane & 3;
    #pragma unroll
    for (int mi = 0; mi < 4; mi++) {
        #pragma unroll
        for (int h = 0; h < 2; h++) {
            int lrow = wm * 64 + mi * 16 + qr + h * 8;
            float ndx2 = -2.f * dxs[lrow];
            __half gm[8];
            #pragma unroll
            for (int nj = 0; nj < 8; nj++) {
                int cl = wn * 64 + nj * 8 + 2 * qc;
                float s0 = fmaf(ndx2 * dws[cl],     (float)acc[mi][nj][h * 2 + 0], w2s[cl]);
                float s1 = fmaf(ndx2 * dws[cl + 1], (float)acc[mi][nj][h * 2 + 1], w2s[cl + 1]);
                float m = fminf(s0, s1);
                m = fminf(m, __shfl_xor_sync(0xFFFFFFFFu, m, 1));
                m = fminf(m, __shfl_xor_sync(0xFFFFFFFFu, m, 2));
                gm[nj] = __float2half(m);
            }
            if (qc == 0) {
                uint4 v;
                __half2 p0 = __halves2half2(gm[0], gm[1]);
                __half2 p1 = __halves2half2(gm[2], gm[3]);
                __half2 p2 = __halves2half2(gm[4], gm[5]);
                __half2 p3 = __halves2half2(gm[6], gm[7]);
                v.x = *reinterpret_cast<uint32_t*>(&p0);
                v.y = *reinterpret_cast<uint32_t*>(&p1);
                v.z = *reinterpret_cast<uint32_t*>(&p2);
                v.w = *reinterpret_cast<uint32_t*>(&p3);
                *reinterpret_cast<uint4*>(
                    g_gmin + (size_t)(row0 + lrow) * NGRP + (col0 >> 3) + wn * 8) = v;
            }
        }
    }
}

// ---------------- refine: group-min scan + exact fp32 re-score ----------------
__global__ void __launch_bounds__(256)
refine_kernel(const float* __restrict__ X, const float* __restrict__ W) {
    __shared__ float s_min[8];
    __shared__ int s_cand[NGRP];     // group ids; cannot overflow (NGRP max)
    __shared__ int s_cnt;
    __shared__ unsigned long long s_best;
    const int b = blockIdx.x, tid = threadIdx.x;
    const int lane = tid & 31, wid = tid >> 5;

    // pass 1: read this row's 2048 group minima (4 KB), block-min
    const uint4 q = reinterpret_cast<const uint4*>(g_gmin + (size_t)b * NGRP)[tid];
    __half2 h0 = *reinterpret_cast<const __half2*>(&q.x);
    __half2 h1 = *reinterpret_cast<const __half2*>(&q.y);
    __half2 h2 = *reinterpret_cast<const __half2*>(&q.z);
    __half2 h3 = *reinterpret_cast<const __half2*>(&q.w);
    __half2 m01 = __hmin2(h0, h1), m23 = __hmin2(h2, h3);
    __half2 mm = __hmin2(m01, m23);
    float mn = fminf(__half2float(__low2half(mm)), __half2float(__high2half(mm)));
    #pragma unroll
    for (int o = 16; o > 0; o >>= 1) mn = fminf(mn, __shfl_xor_sync(0xFFFFFFFFu, mn, o));
    if (lane == 0) s_min[wid] = mn;
    if (tid == 0) { s_cnt = 0; s_best = ~0ULL; }
    __syncthreads();
    if (tid == 0) {
        float m = s_min[0];
        #pragma unroll
        for (int i = 1; i < 8; i++) m = fminf(m, s_min[i]);
        s_min[0] = m;
    }
    __syncthreads();
    const float thr = s_min[0] + MARGIN;

    // collect qualifying groups (each thread owns groups tid*8 .. tid*8+7)
    const __half* hp = reinterpret_cast<const __half*>(&q);
    #pragma unroll
    for (int e = 0; e < 8; e++) {
        if (__half2float(hp[e]) <= thr) {
            int p = atomicAdd(&s_cnt, 1);
            s_cand[p] = tid * 8 + e;
        }
    }
    __syncthreads();
    const int cnt = s_cnt;

    // exact fp32 re-score: one warp per candidate j (8 js per group)
    const float4* x4 = reinterpret_cast<const float4*>(X + (size_t)b * K_IN);
    for (int item = wid; item < cnt * 8; item += 8) {
        int j = s_cand[item >> 3] * 8 + (item & 7);
        const float4* w4 = reinterpret_cast<const float4*>(W + (size_t)j * K_IN);
        float acc = 0.f;
        #pragma unroll
        for (int i = 0; i < 4; i++) {
            float4 a = x4[lane + i * 32], w = w4[lane + i * 32];
            acc += a.x * w.x + a.y * w.y + a.z * w.z + a.w * w.w;
        }
        #pragma unroll
        for (int o = 16; o > 0; o >>= 1) acc += __shfl_xor_sync(0xFFFFFFFFu, acc, o);
        if (lane == 0) {
            float s = fmaf(-2.f, acc, g_w2[j]);
            unsigned long long p =
                ((unsigned long long)f32_key(s) << 32) | (unsigned int)j;
            atomicMin(&s_best, p);
        }
    }
    __syncthreads();
    if (tid == 0) g_packed[b] = s_best;
}

// ---------------- gather grossberg columns ----------------
__global__ void gather_kernel(const float* __restrict__ G, float* __restrict__ out,
                              int out_size) {
    int b = blockIdx.x;
    unsigned int w = (unsigned int)(g_packed[b] & 0xFFFFFFFFull);
    for (int o = threadIdx.x; o < N_OUT; o += blockDim.x)
        out[(size_t)b * N_OUT + o] = G[(size_t)o * H_HID + w];
    if (threadIdx.x == 0 && out_size >= B_BATCH * N_OUT + B_BATCH)
        out[(size_t)B_BATCH * N_OUT + b] = (float)w;
}

// ---------------- launcher ----------------
extern "C" void kernel_launch(void* const* d_in, const int* in_sizes, int n_in,
                              void* d_out, int out_size) {
    const float* x  = (const float*)d_in[0];   // [4096, 512]
    const float* kw = (const float*)d_in[1];   // [16384, 512]
    const float* gw = (const float*)d_in[2];   // [1000, 16384]
    float* out = (float*)d_out;

    cudaFuncSetAttribute(gemm_coarse_kernel,
                         cudaFuncAttributeMaxDynamicSharedMemorySize, GEMM_SMEM);

    prep_x_kernel<<<B_BATCH / 8, 256>>>(x);
    prep_w_kernel<<<H_HID / 8, 256>>>(kw);

    dim3 grid(B_BATCH / BM, H_HID / BN);   // (32, 64)
    gemm_coarse_kernel<<<grid, THREADS, GEMM_SMEM>>>();

    refine_kernel<<<B_BATCH, 256>>>(x, kw);
    gather_kernel<<<B_BATCH, 256>>>(gw, out, out_size);
}